// round 11
// baseline (speedup 1.0000x reference)
#include <cuda_runtime.h>
#include <math.h>
#include <stdint.h>

#define NUM_CLASSES 10
#define BLOCK 256
#define WARPS_PER_BLOCK (BLOCK / 32)
#define BLOCKS_PER_SM 5
#define GRID (148 * BLOCKS_PER_SM)             // 740 — co-resident via launch_bounds
#define NTHREADS (GRID * BLOCK)
#define TOTAL_WARPS (GRID * WARPS_PER_BLOCK)   // 5920
#define CHUNK_ROWS 64                          // per warp-iter: 64 rows = 2560 B

// log(x) = logf(x * 2^-21) + 21*ln2  (shift folded into final math)
#define LOG_SCALE (4.76837158203125e-7f)   // 2^-21
#define LOG_SHIFT 21.0

__device__ float  g_hist_partial[GRID * NUM_CLASSES];
__device__ double g_partial_log[GRID];
__device__ double g_partial_sq[GRID];
__device__ unsigned int g_hist_ready = 0;  // reset by last block each run
__device__ unsigned int g_done = 0;        // reset by last block each run

// ---- packed f32x2 helpers (Blackwell) --------------------------------------
__device__ __forceinline__ unsigned long long ffma2(unsigned long long a,
                                                    unsigned long long b,
                                                    unsigned long long c) {
    unsigned long long d;
    asm("fma.rn.f32x2 %0, %1, %2, %3;" : "=l"(d) : "l"(a), "l"(b), "l"(c));
    return d;
}
__device__ __forceinline__ unsigned long long fmul2(unsigned long long a,
                                                    unsigned long long b) {
    unsigned long long d;
    asm("mul.rn.f32x2 %0, %1, %2;" : "=l"(d) : "l"(a), "l"(b));
    return d;
}
__device__ __forceinline__ unsigned long long fpack2(float lo, float hi) {
    unsigned long long d;
    asm("mov.b64 %0, {%1, %2};" : "=l"(d) : "f"(lo), "f"(hi));
    return d;
}
__device__ __forceinline__ float funpack_sum(unsigned long long d) {
    float lo, hi;
    asm("mov.b64 {%0, %1}, %2;" : "=f"(lo), "=f"(hi) : "l"(d));
    return lo + hi;
}

__global__ void __launch_bounds__(BLOCK, BLOCKS_PER_SM)
cse_fused_kernel(const float* __restrict__ outp, const int* __restrict__ tgt,
                 int n_rows, float* __restrict__ out) {
    // per-warp private staging regions — no cross-warp sharing in phase B
    __shared__ __align__(16) float s_stage[WARPS_PER_BLOCK][CHUNK_ROWS * NUM_CLASSES];
    __shared__ unsigned int s_hist[NUM_CLASSES];
    __shared__ float  s_cnt[NUM_CLASSES];
    __shared__ double s_rl[WARPS_PER_BLOCK];
    __shared__ double s_rq[WARPS_PER_BLOCK];
    __shared__ bool s_last;

    const int tid  = threadIdx.x;
    const int bid  = blockIdx.x;
    const int wid  = tid >> 5;
    const int lane = tid & 31;

    // ================= Phase A: histogram of target (int32 in [0,10)) ======
    if (tid < NUM_CLASSES) { s_hist[tid] = 0u; s_cnt[tid] = 0.0f; }
    __syncthreads();
    {
        unsigned int c[NUM_CLASSES];
#pragma unroll
        for (int j = 0; j < NUM_CLASSES; j++) c[j] = 0u;

        const int4* t4 = reinterpret_cast<const int4*>(tgt);
        const int n4 = n_rows >> 2;
        unsigned long long acc = 0ull;
        int since = 0;
        for (int i = bid * BLOCK + tid; i < n4; i += NTHREADS) {
            int4 v = __ldcs(&t4[i]);
            acc += 1ull << (6 * v.x);
            acc += 1ull << (6 * v.y);
            acc += 1ull << (6 * v.z);
            acc += 1ull << (6 * v.w);
            if (++since == 10) {          // <=40 increments per 6-bit field
#pragma unroll
                for (int j = 0; j < NUM_CLASSES; j++)
                    c[j] += (unsigned int)((acc >> (6 * j)) & 63ull);
                acc = 0ull; since = 0;
            }
        }
        if (since) {
#pragma unroll
            for (int j = 0; j < NUM_CLASSES; j++)
                c[j] += (unsigned int)((acc >> (6 * j)) & 63ull);
        }
        if (bid == 0 && tid == 0) {       // tail rows (n % 4)
            for (int r = (n_rows >> 2) << 2; r < n_rows; r++) c[tgt[r]]++;
        }
#pragma unroll
        for (int j = 0; j < NUM_CLASSES; j++)
            if (c[j]) atomicAdd(&s_hist[j], c[j]);
    }
    __syncthreads();
    if (tid < NUM_CLASSES)
        g_hist_partial[bid * NUM_CLASSES + tid] = (float)s_hist[tid];
    __threadfence();
    if (tid == 0) {
        atomicAdd(&g_hist_ready, 1u);
        while (*(volatile unsigned int*)&g_hist_ready < (unsigned int)GRID)
            __nanosleep(64);
        __threadfence();
    }
    __syncthreads();

    // reduce partials -> class counts (exact small integers in float)
    for (int idx = tid; idx < GRID * NUM_CLASSES; idx += BLOCK)
        atomicAdd(&s_cnt[idx % NUM_CLASSES], g_hist_partial[idx]);
    __syncthreads();

    // packed class-count pairs {c0,c1},{c2,c3},{c4,c5},{c6,c7},{c8,c9}
    const unsigned long long cp0 = fpack2(s_cnt[0], s_cnt[1]);
    const unsigned long long cp1 = fpack2(s_cnt[2], s_cnt[3]);
    const unsigned long long cp2 = fpack2(s_cnt[4], s_cnt[5]);
    const unsigned long long cp3 = fpack2(s_cnt[6], s_cnt[7]);
    const unsigned long long cp4 = fpack2(s_cnt[8], s_cnt[9]);

    // ================= Phase B: warp-autonomous streaming ===================
    // Per warp-iter: 64 rows. 5 front-batched coalesced LDG.128 -> private
    // smem region -> syncwarp -> conflict-free LDS (ulonglong2 = packed f32
    // pairs) -> packed f32x2 math. NO block barriers. 40 warps/SM.
    const float4* __restrict__ in4 = reinterpret_cast<const float4*>(outp);
    float4* sreg4 = reinterpret_cast<float4*>(&s_stage[wid][0]);
    const int n_chunks = n_rows / CHUNK_ROWS;
    const int gwarp = bid * WARPS_PER_BLOCK + wid;

    double acc_log = 0.0;
    unsigned long long sq2 = 0ull;        // packed f32x2 sum-of-squares accumulator
    float  prod    = 1.0f;
    int    pcnt    = 0;

    for (int ch = gwarp; ch < n_chunks; ch += TOTAL_WARPS) {
        const float4* g = in4 + (size_t)ch * (CHUNK_ROWS * NUM_CLASSES / 4) + lane;
        float4 r0 = __ldcs(g + 0 * 32);
        float4 r1 = __ldcs(g + 1 * 32);
        float4 r2 = __ldcs(g + 2 * 32);
        float4 r3 = __ldcs(g + 3 * 32);
        float4 r4 = __ldcs(g + 4 * 32);
        sreg4[lane + 0 * 32] = r0;
        sreg4[lane + 1 * 32] = r1;
        sreg4[lane + 2 * 32] = r2;
        sreg4[lane + 3 * 32] = r3;
        sreg4[lane + 4 * 32] = r4;
        __syncwarp();

        // this lane's 2 rows as 10 packed f32 pairs (LDS.128, conflict-free)
        const ulonglong2* my =
            reinterpret_cast<const ulonglong2*>(&s_stage[wid][0]) + lane * 5;
        ulonglong2 p0 = my[0];
        ulonglong2 p1 = my[1];
        ulonglong2 p2 = my[2];
        ulonglong2 p3 = my[3];
        ulonglong2 p4 = my[4];

        // dot products via packed FMA (5 FFMA2 each)
        unsigned long long d0 = fmul2(p0.x, cp0);
        d0 = ffma2(p0.y, cp1, d0);
        d0 = ffma2(p1.x, cp2, d0);
        d0 = ffma2(p1.y, cp3, d0);
        d0 = ffma2(p2.x, cp4, d0);
        unsigned long long d1 = fmul2(p2.y, cp0);
        d1 = ffma2(p3.x, cp1, d1);
        d1 = ffma2(p3.y, cp2, d1);
        d1 = ffma2(p4.x, cp3, d1);
        d1 = ffma2(p4.y, cp4, d1);

        // sum of squares: 10 packed FMAs into running pair accumulator
        sq2 = ffma2(p0.x, p0.x, sq2);
        sq2 = ffma2(p0.y, p0.y, sq2);
        sq2 = ffma2(p1.x, p1.x, sq2);
        sq2 = ffma2(p1.y, p1.y, sq2);
        sq2 = ffma2(p2.x, p2.x, sq2);
        sq2 = ffma2(p2.y, p2.y, sq2);
        sq2 = ffma2(p3.x, p3.x, sq2);
        sq2 = ffma2(p3.y, p3.y, sq2);
        sq2 = ffma2(p4.x, p4.x, sq2);
        sq2 = ffma2(p4.y, p4.y, sq2);

        float dot0 = funpack_sum(d0);
        float dot1 = funpack_sum(d1);

        prod *= dot0 * LOG_SCALE;
        if (++pcnt == 8) { acc_log += (double)logf(prod); prod = 1.0f; pcnt = 0; }
        prod *= dot1 * LOG_SCALE;
        if (++pcnt == 8) { acc_log += (double)logf(prod); prod = 1.0f; pcnt = 0; }

        __syncwarp();                    // region free for next iteration's STS
    }

    double acc_sq = (double)funpack_sum(sq2);

    // tail rows (n_rows % CHUNK_ROWS) directly from gmem, block 0
    const int n_chunks_total = n_rows / CHUNK_ROWS;
    const int tail_start = n_chunks_total * CHUNK_ROWS;
    if (bid == 0) {
        float cs[NUM_CLASSES];
#pragma unroll
        for (int j = 0; j < NUM_CLASSES; j++) cs[j] = s_cnt[j];
        for (int r = tail_start + tid; r < n_rows; r += BLOCK) {
            const float* row = outp + (size_t)r * NUM_CLASSES;
            float dot = 0.f, sq = 0.f;
#pragma unroll
            for (int j = 0; j < NUM_CLASSES; j++) {
                float x = row[j];
                dot = fmaf(x, cs[j], dot);
                sq  = fmaf(x, x, sq);
            }
            acc_sq  += (double)sq;
            acc_log += (double)logf(dot * LOG_SCALE);
        }
    }

    if (pcnt) acc_log += (double)logf(prod);

    // ================= block reduction (deterministic order) ===============
#pragma unroll
    for (int off = 16; off; off >>= 1) {
        acc_log += __shfl_down_sync(0xffffffffu, acc_log, off);
        acc_sq  += __shfl_down_sync(0xffffffffu, acc_sq,  off);
    }
    if (lane == 0) { s_rl[wid] = acc_log; s_rq[wid] = acc_sq; }
    __syncthreads();
    if (tid == 0) {
        double a = 0.0, b = 0.0;
#pragma unroll
        for (int w = 0; w < WARPS_PER_BLOCK; w++) { a += s_rl[w]; b += s_rq[w]; }
        g_partial_log[bid] = a;
        g_partial_sq[bid]  = b;
        __threadfence();
        unsigned int tkt = atomicAdd(&g_done, 1u);
        s_last = (tkt == (unsigned int)(GRID - 1));
    }
    __syncthreads();

    // ================= last block: final scalar =============================
    if (s_last) {
        __threadfence();
        double a = 0.0, b = 0.0;
        for (int i = tid; i < GRID; i += BLOCK) {
            a += g_partial_log[i];
            b += g_partial_sq[i];
        }
#pragma unroll
        for (int off = 16; off; off >>= 1) {
            a += __shfl_down_sync(0xffffffffu, a, off);
            b += __shfl_down_sync(0xffffffffu, b, off);
        }
        if (lane == 0) { s_rl[wid] = a; s_rq[wid] = b; }
        __syncthreads();
        if (tid == 0) {
            double sa = 0.0, sb = 0.0;
#pragma unroll
            for (int w = 0; w < WARPS_PER_BLOCK; w++) { sa += s_rl[w]; sb += s_rq[w]; }
            double N = (double)n_rows;
            double mean_log_nom = sa / N + LOG_SHIFT * M_LN2;
            double log_denom = 0.5 * log(sb) + 0.5 * log(N);   // log(||o||_F * sqrt(N))
            out[0] = (float)(log_denom - mean_log_nom);
            g_done = 0;         // reset for next graph replay
            g_hist_ready = 0;
        }
    }
}

extern "C" void kernel_launch(void* const* d_in, const int* in_sizes, int n_in,
                              void* d_out, int out_size) {
    // Resolve inputs by size: outputs has NUM_CLASSES x the elements of target.
    int io = 0, it = 1;
    if (n_in >= 2 && in_sizes[1] > in_sizes[0]) { io = 1; it = 0; }
    const float* outputs = (const float*)d_in[io];
    const int*   tgt     = (const int*)d_in[it];      // int32
    const int    n_rows  = in_sizes[it];              // N samples
    float* out           = (float*)d_out;

    cse_fused_kernel<<<GRID, BLOCK>>>(outputs, tgt, n_rows, out);
}

// round 12
// speedup vs baseline: 1.1305x; 1.1305x over previous
#include <cuda_runtime.h>
#include <math.h>
#include <stdint.h>

#define NUM_CLASSES 10
#define BLOCK 256
#define BLOCKS_PER_SM 4
#define GRID (148 * BLOCKS_PER_SM)             // 592 — co-resident via launch_bounds
#define NTHREADS (GRID * BLOCK)
#define TILE_ROWS 512
#define TILE_F4 (TILE_ROWS * NUM_CLASSES / 4)  // 1280 float4 per tile

// log(x) = logf(x * 2^-21) + 21*ln2  (shift folded into final math)
#define LOG_SCALE (4.76837158203125e-7f)   // 2^-21
#define LOG_SHIFT 21.0

__device__ float  g_hist_partial[GRID * NUM_CLASSES];
__device__ double g_partial_log[GRID];
__device__ double g_partial_sq[GRID];
__device__ unsigned int g_hist_ready = 0;  // reset by last block each run
__device__ unsigned int g_done = 0;        // reset by last block each run

// ---- packed f32x2 helpers (Blackwell) --------------------------------------
__device__ __forceinline__ unsigned long long ffma2(unsigned long long a,
                                                    unsigned long long b,
                                                    unsigned long long c) {
    unsigned long long d;
    asm("fma.rn.f32x2 %0, %1, %2, %3;" : "=l"(d) : "l"(a), "l"(b), "l"(c));
    return d;
}
__device__ __forceinline__ unsigned long long fmul2(unsigned long long a,
                                                    unsigned long long b) {
    unsigned long long d;
    asm("mul.rn.f32x2 %0, %1, %2;" : "=l"(d) : "l"(a), "l"(b));
    return d;
}
__device__ __forceinline__ unsigned long long fpack2(float lo, float hi) {
    unsigned long long d;
    asm("mov.b64 %0, {%1, %2};" : "=l"(d) : "f"(lo), "f"(hi));
    return d;
}
__device__ __forceinline__ float funpack_sum(unsigned long long d) {
    float lo, hi;
    asm("mov.b64 {%0, %1}, %2;" : "=f"(lo), "=f"(hi) : "l"(d));
    return lo + hi;
}

__global__ void __launch_bounds__(BLOCK, BLOCKS_PER_SM)
cse_fused_kernel(const float* __restrict__ outp, const int* __restrict__ tgt,
                 int n_rows, float* __restrict__ out) {
    __shared__ __align__(16) float s_tile[TILE_ROWS * NUM_CLASSES];   // 20480 B
    __shared__ unsigned int s_hist[NUM_CLASSES];
    __shared__ float  s_cnt[NUM_CLASSES];
    __shared__ double s_rl[BLOCK / 32];
    __shared__ double s_rq[BLOCK / 32];
    __shared__ bool s_last;

    const int tid  = threadIdx.x;
    const int bid  = blockIdx.x;
    const int wid  = tid >> 5;
    const int lane = tid & 31;

    // ================= Phase A: histogram of target (int32 in [0,10)) ======
    if (tid < NUM_CLASSES) { s_hist[tid] = 0u; s_cnt[tid] = 0.0f; }
    __syncthreads();
    {
        unsigned int c[NUM_CLASSES];
#pragma unroll
        for (int j = 0; j < NUM_CLASSES; j++) c[j] = 0u;

        const int4* t4 = reinterpret_cast<const int4*>(tgt);
        const int n4 = n_rows >> 2;
        unsigned long long acc = 0ull;
        int since = 0;
        for (int i = bid * BLOCK + tid; i < n4; i += NTHREADS) {
            int4 v = __ldcs(&t4[i]);
            acc += 1ull << (6 * v.x);
            acc += 1ull << (6 * v.y);
            acc += 1ull << (6 * v.z);
            acc += 1ull << (6 * v.w);
            if (++since == 10) {          // <=40 increments per 6-bit field
#pragma unroll
                for (int j = 0; j < NUM_CLASSES; j++)
                    c[j] += (unsigned int)((acc >> (6 * j)) & 63ull);
                acc = 0ull; since = 0;
            }
        }
        if (since) {
#pragma unroll
            for (int j = 0; j < NUM_CLASSES; j++)
                c[j] += (unsigned int)((acc >> (6 * j)) & 63ull);
        }
        if (bid == 0 && tid == 0) {       // tail rows (n % 4)
            for (int r = (n_rows >> 2) << 2; r < n_rows; r++) c[tgt[r]]++;
        }
#pragma unroll
        for (int j = 0; j < NUM_CLASSES; j++)
            if (c[j]) atomicAdd(&s_hist[j], c[j]);
    }
    __syncthreads();
    if (tid < NUM_CLASSES)
        g_hist_partial[bid * NUM_CLASSES + tid] = (float)s_hist[tid];
    __threadfence();
    if (tid == 0) {
        atomicAdd(&g_hist_ready, 1u);
        while (*(volatile unsigned int*)&g_hist_ready < (unsigned int)GRID)
            __nanosleep(64);
        __threadfence();
    }
    __syncthreads();

    // reduce partials -> class counts (exact small integers in float)
    for (int idx = tid; idx < GRID * NUM_CLASSES; idx += BLOCK)
        atomicAdd(&s_cnt[idx % NUM_CLASSES], g_hist_partial[idx]);
    __syncthreads();

    // packed class-count pairs {c0,c1},{c2,c3},{c4,c5},{c6,c7},{c8,c9}
    const unsigned long long cp0 = fpack2(s_cnt[0], s_cnt[1]);
    const unsigned long long cp1 = fpack2(s_cnt[2], s_cnt[3]);
    const unsigned long long cp2 = fpack2(s_cnt[4], s_cnt[5]);
    const unsigned long long cp3 = fpack2(s_cnt[6], s_cnt[7]);
    const unsigned long long cp4 = fpack2(s_cnt[8], s_cnt[9]);

    // ================= Phase B: R3 block-staged tile loop (best measured) ===
    const float4* __restrict__ in4 = reinterpret_cast<const float4*>(outp);
    float4* s4 = reinterpret_cast<float4*>(s_tile);
    const int n_tiles = n_rows / TILE_ROWS;

    double acc_log = 0.0;
    unsigned long long sq2 = 0ull;        // packed f32x2 sum-of-squares accumulator
    float  prod    = 1.0f;
    int    pcnt    = 0;

    for (int t = bid; t < n_tiles; t += GRID) {
        const float4* g = in4 + (size_t)t * TILE_F4 + tid;
        // coalesced stage: 5 LDG.128 -> STS.128
        s4[tid + 0 * BLOCK] = __ldcs(g + 0 * BLOCK);
        s4[tid + 1 * BLOCK] = __ldcs(g + 1 * BLOCK);
        s4[tid + 2 * BLOCK] = __ldcs(g + 2 * BLOCK);
        s4[tid + 3 * BLOCK] = __ldcs(g + 3 * BLOCK);
        s4[tid + 4 * BLOCK] = __ldcs(g + 4 * BLOCK);
        __syncthreads();

        // this thread's 2 rows as 10 packed f32 pairs (LDS.128, conflict-free)
        const ulonglong2* my = reinterpret_cast<const ulonglong2*>(s_tile) + tid * 5;
        ulonglong2 p0 = my[0];
        ulonglong2 p1 = my[1];
        ulonglong2 p2 = my[2];
        ulonglong2 p3 = my[3];
        ulonglong2 p4 = my[4];

        // dot products via packed FMA (5 FFMA2 each)
        unsigned long long d0 = fmul2(p0.x, cp0);
        d0 = ffma2(p0.y, cp1, d0);
        d0 = ffma2(p1.x, cp2, d0);
        d0 = ffma2(p1.y, cp3, d0);
        d0 = ffma2(p2.x, cp4, d0);
        unsigned long long d1 = fmul2(p2.y, cp0);
        d1 = ffma2(p3.x, cp1, d1);
        d1 = ffma2(p3.y, cp2, d1);
        d1 = ffma2(p4.x, cp3, d1);
        d1 = ffma2(p4.y, cp4, d1);

        // sum of squares: 10 packed FMAs into running pair accumulator
        sq2 = ffma2(p0.x, p0.x, sq2);
        sq2 = ffma2(p0.y, p0.y, sq2);
        sq2 = ffma2(p1.x, p1.x, sq2);
        sq2 = ffma2(p1.y, p1.y, sq2);
        sq2 = ffma2(p2.x, p2.x, sq2);
        sq2 = ffma2(p2.y, p2.y, sq2);
        sq2 = ffma2(p3.x, p3.x, sq2);
        sq2 = ffma2(p3.y, p3.y, sq2);
        sq2 = ffma2(p4.x, p4.x, sq2);
        sq2 = ffma2(p4.y, p4.y, sq2);

        float dot0 = funpack_sum(d0);
        float dot1 = funpack_sum(d1);

        prod *= dot0 * LOG_SCALE;
        if (++pcnt == 8) { acc_log += (double)logf(prod); prod = 1.0f; pcnt = 0; }
        prod *= dot1 * LOG_SCALE;
        if (++pcnt == 8) { acc_log += (double)logf(prod); prod = 1.0f; pcnt = 0; }

        __syncthreads();                  // tile buffer free for next iteration
    }

    double acc_sq = (double)funpack_sum(sq2);

    // tail rows (n_rows % TILE_ROWS) directly from gmem, block 0
    const int tail_start = n_tiles * TILE_ROWS;
    if (bid == 0) {
        float cs[NUM_CLASSES];
#pragma unroll
        for (int j = 0; j < NUM_CLASSES; j++) cs[j] = s_cnt[j];
        for (int r = tail_start + tid; r < n_rows; r += BLOCK) {
            const float* row = outp + (size_t)r * NUM_CLASSES;
            float dot = 0.f, sq = 0.f;
#pragma unroll
            for (int j = 0; j < NUM_CLASSES; j++) {
                float x = row[j];
                dot = fmaf(x, cs[j], dot);
                sq  = fmaf(x, x, sq);
            }
            acc_sq  += (double)sq;
            acc_log += (double)logf(dot * LOG_SCALE);
        }
    }

    if (pcnt) acc_log += (double)logf(prod);

    // ================= block reduction (deterministic order) ===============
#pragma unroll
    for (int off = 16; off; off >>= 1) {
        acc_log += __shfl_down_sync(0xffffffffu, acc_log, off);
        acc_sq  += __shfl_down_sync(0xffffffffu, acc_sq,  off);
    }
    if (lane == 0) { s_rl[wid] = acc_log; s_rq[wid] = acc_sq; }
    __syncthreads();
    if (tid == 0) {
        double a = 0.0, b = 0.0;
#pragma unroll
        for (int w = 0; w < BLOCK / 32; w++) { a += s_rl[w]; b += s_rq[w]; }
        g_partial_log[bid] = a;
        g_partial_sq[bid]  = b;
        __threadfence();
        unsigned int tkt = atomicAdd(&g_done, 1u);
        s_last = (tkt == (unsigned int)(GRID - 1));
    }
    __syncthreads();

    // ================= last block: final scalar =============================
    if (s_last) {
        __threadfence();
        double a = 0.0, b = 0.0;
        for (int i = tid; i < GRID; i += BLOCK) {
            a += g_partial_log[i];
            b += g_partial_sq[i];
        }
#pragma unroll
        for (int off = 16; off; off >>= 1) {
            a += __shfl_down_sync(0xffffffffu, a, off);
            b += __shfl_down_sync(0xffffffffu, b, off);
        }
        if (lane == 0) { s_rl[wid] = a; s_rq[wid] = b; }
        __syncthreads();
        if (tid == 0) {
            double sa = 0.0, sb = 0.0;
#pragma unroll
            for (int w = 0; w < BLOCK / 32; w++) { sa += s_rl[w]; sb += s_rq[w]; }
            double N = (double)n_rows;
            double mean_log_nom = sa / N + LOG_SHIFT * M_LN2;
            double log_denom = 0.5 * log(sb) + 0.5 * log(N);   // log(||o||_F * sqrt(N))
            out[0] = (float)(log_denom - mean_log_nom);
            g_done = 0;         // reset for next graph replay
            g_hist_ready = 0;
        }
    }
}

extern "C" void kernel_launch(void* const* d_in, const int* in_sizes, int n_in,
                              void* d_out, int out_size) {
    // Resolve inputs by size: outputs has NUM_CLASSES x the elements of target.
    int io = 0, it = 1;
    if (n_in >= 2 && in_sizes[1] > in_sizes[0]) { io = 1; it = 0; }
    const float* outputs = (const float*)d_in[io];
    const int*   tgt     = (const int*)d_in[it];      // int32
    const int    n_rows  = in_sizes[it];              // N samples
    float* out           = (float*)d_out;

    cse_fused_kernel<<<GRID, BLOCK>>>(outputs, tgt, n_rows, out);
}

// round 13
// speedup vs baseline: 1.2557x; 1.1107x over previous
#include <cuda_runtime.h>
#include <math.h>
#include <stdint.h>

#define NUM_CLASSES 10
#define BLOCK 256
#define GRID_MAIN 592
#define GRID_HIST 592
#define TILE_ROWS 512
#define TILE_F4 (TILE_ROWS * NUM_CLASSES / 4)   // 1280 float4 per tile

// log(x) = logf(x * 2^-21) + 21*ln2  (shift folded into final math)
#define LOG_SCALE (4.76837158203125e-7f)   // 2^-21
#define LOG_SHIFT 21.0

__device__ float  g_hist_partial[GRID_HIST * NUM_CLASSES];
__device__ float  g_counts[NUM_CLASSES];
__device__ double g_partial_log[GRID_MAIN];
__device__ double g_partial_sq[GRID_MAIN];
__device__ unsigned int g_hist_done = 0;   // reset by hist's last block each run
__device__ unsigned int g_done = 0;        // reset by main's last block each run

// ---------------------------------------------------------------------------
// Histogram of target (int32 in [0,10)) -> per-block partials -> ticket ->
// last block reduces into g_counts. No init kernel, no residency assumption.
// ---------------------------------------------------------------------------
__global__ void __launch_bounds__(BLOCK)
cse_hist_kernel(const int* __restrict__ tgt, int n) {
    __shared__ unsigned int s_hist[NUM_CLASSES];
    __shared__ bool s_last;
    const int tid = threadIdx.x;
    const int bid = blockIdx.x;
    if (tid < NUM_CLASSES) s_hist[tid] = 0u;
    __syncthreads();

    unsigned int c[NUM_CLASSES];
#pragma unroll
    for (int j = 0; j < NUM_CLASSES; j++) c[j] = 0u;

    const int4* t4 = reinterpret_cast<const int4*>(tgt);
    const int n4 = n >> 2;
    const int stride = GRID_HIST * BLOCK;

    // two independent packed-u64 streams -> 2x MLP on this latency-bound loop
    unsigned long long accA = 0ull, accB = 0ull;
    int since = 0;
    int i = bid * BLOCK + tid;
    for (; i + stride < n4; i += 2 * stride) {
        int4 va = t4[i];
        int4 vb = t4[i + stride];
        accA += (1ull << (6 * va.x)) + (1ull << (6 * va.y)) +
                (1ull << (6 * va.z)) + (1ull << (6 * va.w));
        accB += (1ull << (6 * vb.x)) + (1ull << (6 * vb.y)) +
                (1ull << (6 * vb.z)) + (1ull << (6 * vb.w));
        if (++since == 10) {              // <=40 increments per 6-bit field
#pragma unroll
            for (int j = 0; j < NUM_CLASSES; j++) {
                c[j] += (unsigned int)((accA >> (6 * j)) & 63ull);
                c[j] += (unsigned int)((accB >> (6 * j)) & 63ull);
            }
            accA = 0ull; accB = 0ull; since = 0;
        }
    }
    if (i < n4) {
        int4 va = t4[i];
        accA += (1ull << (6 * va.x)) + (1ull << (6 * va.y)) +
                (1ull << (6 * va.z)) + (1ull << (6 * va.w));
    }
#pragma unroll
    for (int j = 0; j < NUM_CLASSES; j++) {
        c[j] += (unsigned int)((accA >> (6 * j)) & 63ull);
        c[j] += (unsigned int)((accB >> (6 * j)) & 63ull);
    }
    if (bid == 0 && tid == 0) {           // tail rows (n % 4)
        for (int r = n4 * 4; r < n; r++) c[tgt[r]]++;
    }
#pragma unroll
    for (int j = 0; j < NUM_CLASSES; j++)
        if (c[j]) atomicAdd(&s_hist[j], c[j]);
    __syncthreads();
    if (tid < NUM_CLASSES)
        g_hist_partial[bid * NUM_CLASSES + tid] = (float)s_hist[tid];
    __threadfence();
    if (tid == 0) {
        unsigned int tkt = atomicAdd(&g_hist_done, 1u);
        s_last = (tkt == (unsigned int)(GRID_HIST - 1));
    }
    __syncthreads();
    if (s_last) {
        __threadfence();
        if (tid < NUM_CLASSES) {
            float sum = 0.0f;
            for (int b = 0; b < GRID_HIST; b++)
                sum += g_hist_partial[b * NUM_CLASSES + tid];
            g_counts[tid] = sum;
        }
        if (tid == 0) g_hist_done = 0;    // reset for next graph replay
    }
}

// ---------------------------------------------------------------------------
// Main kernel: R3's exact phase B (plain cached loads, block-staged tiles) +
// inline ticket finalize (no separate finalize launch).
// ---------------------------------------------------------------------------
__global__ void __launch_bounds__(BLOCK, 1)
cse_main_kernel(const float* __restrict__ outp, int n_rows, float* __restrict__ out) {
    __shared__ __align__(16) float s_tile[TILE_ROWS * NUM_CLASSES]; // 20480 B
    __shared__ float s_cnt[NUM_CLASSES];
    __shared__ double s_rl[BLOCK / 32];
    __shared__ double s_rq[BLOCK / 32];
    __shared__ bool s_last;

    const int tid = threadIdx.x;
    const int bid = blockIdx.x;
    if (tid < NUM_CLASSES) s_cnt[tid] = g_counts[tid];
    __syncthreads();

    float c[NUM_CLASSES];
#pragma unroll
    for (int j = 0; j < NUM_CLASSES; j++) c[j] = s_cnt[j];

    const float4* __restrict__ in4 = reinterpret_cast<const float4*>(outp);
    float4* s4 = reinterpret_cast<float4*>(s_tile);

    const int n_tiles = n_rows / TILE_ROWS;

    double acc_log = 0.0;
    double acc_sq  = 0.0;
    float  prod    = 1.0f;
    int    pcnt    = 0;

    for (int tile = bid; tile < n_tiles; tile += GRID_MAIN) {
        size_t base4 = (size_t)tile * TILE_F4;
#pragma unroll
        for (int k = 0; k < 5; k++) {
            s4[tid + k * BLOCK] = in4[base4 + tid + k * BLOCK];
        }
        __syncthreads();

        // this thread's 2 rows: 20 floats, 16B-aligned (80B per thread)
        const float4* my = reinterpret_cast<const float4*>(s_tile + tid * 2 * NUM_CLASSES);
        float v[20];
#pragma unroll
        for (int k = 0; k < 5; k++) {
            float4 t = my[k];
            v[4 * k + 0] = t.x; v[4 * k + 1] = t.y;
            v[4 * k + 2] = t.z; v[4 * k + 3] = t.w;
        }

        float dot0 = 0.f, dot1 = 0.f, sq = 0.f;
#pragma unroll
        for (int j = 0; j < NUM_CLASSES; j++) {
            dot0 = fmaf(v[j], c[j], dot0);
            dot1 = fmaf(v[NUM_CLASSES + j], c[j], dot1);
        }
#pragma unroll
        for (int k = 0; k < 20; k++) sq = fmaf(v[k], v[k], sq);
        acc_sq += (double)sq;

        prod *= dot0 * LOG_SCALE;
        if (++pcnt == 8) { acc_log += (double)logf(prod); prod = 1.0f; pcnt = 0; }
        prod *= dot1 * LOG_SCALE;
        if (++pcnt == 8) { acc_log += (double)logf(prod); prod = 1.0f; pcnt = 0; }

        __syncthreads();
    }

    // tail rows (n_rows % TILE_ROWS), handled by block 0 directly from gmem
    const int tail_start = n_tiles * TILE_ROWS;
    if (bid == 0) {
        for (int r = tail_start + tid; r < n_rows; r += BLOCK) {
            const float* row = outp + (size_t)r * NUM_CLASSES;
            float dot = 0.f, sq = 0.f;
#pragma unroll
            for (int j = 0; j < NUM_CLASSES; j++) {
                float x = row[j];
                dot = fmaf(x, c[j], dot);
                sq  = fmaf(x, x, sq);
            }
            acc_sq  += (double)sq;
            acc_log += (double)logf(dot * LOG_SCALE);
        }
    }

    if (pcnt) acc_log += (double)logf(prod);

    // block reduction (deterministic order)
#pragma unroll
    for (int off = 16; off; off >>= 1) {
        acc_log += __shfl_down_sync(0xffffffffu, acc_log, off);
        acc_sq  += __shfl_down_sync(0xffffffffu, acc_sq,  off);
    }
    const int wid = tid >> 5, lane = tid & 31;
    if (lane == 0) { s_rl[wid] = acc_log; s_rq[wid] = acc_sq; }
    __syncthreads();
    if (tid == 0) {
        double a = 0.0, b = 0.0;
#pragma unroll
        for (int w = 0; w < BLOCK / 32; w++) { a += s_rl[w]; b += s_rq[w]; }
        g_partial_log[bid] = a;
        g_partial_sq[bid]  = b;
        __threadfence();
        unsigned int tkt = atomicAdd(&g_done, 1u);
        s_last = (tkt == (unsigned int)(GRID_MAIN - 1));
    }
    __syncthreads();

    // last-to-finish block: final reduction + scalar (no extra kernel launch)
    if (s_last) {
        __threadfence();
        double a = 0.0, b = 0.0;
        for (int i = tid; i < GRID_MAIN; i += BLOCK) {
            a += g_partial_log[i];
            b += g_partial_sq[i];
        }
#pragma unroll
        for (int off = 16; off; off >>= 1) {
            a += __shfl_down_sync(0xffffffffu, a, off);
            b += __shfl_down_sync(0xffffffffu, b, off);
        }
        if (lane == 0) { s_rl[wid] = a; s_rq[wid] = b; }
        __syncthreads();
        if (tid == 0) {
            double sa = 0.0, sb = 0.0;
#pragma unroll
            for (int w = 0; w < BLOCK / 32; w++) { sa += s_rl[w]; sb += s_rq[w]; }
            double N = (double)n_rows;
            double mean_log_nom = sa / N + LOG_SHIFT * M_LN2;
            double log_denom = 0.5 * log(sb) + 0.5 * log(N);   // log(||o||_F * sqrt(N))
            out[0] = (float)(log_denom - mean_log_nom);
            g_done = 0;        // reset for next graph replay
        }
    }
}

extern "C" void kernel_launch(void* const* d_in, const int* in_sizes, int n_in,
                              void* d_out, int out_size) {
    // Resolve inputs by size: outputs has NUM_CLASSES x the elements of target.
    int io = 0, it = 1;
    if (n_in >= 2 && in_sizes[1] > in_sizes[0]) { io = 1; it = 0; }
    const float* outputs = (const float*)d_in[io];
    const int*   tgt     = (const int*)d_in[it];      // int32
    const int    n_rows  = in_sizes[it];              // N samples
    float* out           = (float*)d_out;

    cse_hist_kernel<<<GRID_HIST, BLOCK>>>(tgt, n_rows);
    cse_main_kernel<<<GRID_MAIN, BLOCK>>>(outputs, n_rows, out);
}